// round 12
// baseline (speedup 1.0000x reference)
#include <cuda_runtime.h>
#include <cuda_fp16.h>
#include <cstdint>

// ============================================================================
// out[m,n] = sum_k x[m,k] * (w[k/128, k%128, n] * scaler[k/128, n])
//   x: [2,1024,4096] f32 (M=2048,K=4096)  w: [32,128,4096] INT32  sc: [32,4096]
//
// R12: GEMM core = verified R9 (tensor-pipe ceiling), but B is kept n-major
// (wt[k][n]) and loaded via ldmatrix.x4.trans -> the prep transpose (4-way
// LDS-conflicted) disappears; dequant becomes pure streaming.
//   trans fragment map: m0..m3 -> r0..r3; n-lo mma uses (r0,r2), n-hi (r1,r3).
//   B smem: 64 k-rows x 256B, swizzle chunk j ^= (k&7)<<1 (ks/i-invariant).
// ============================================================================

static constexpr int M = 2048;
static constexpr int N = 4096;
static constexpr int K = 4096;

static constexpr int BM = 128;
static constexpr int BN = 128;
static constexpr int BK = 64;
static constexpr int STAGES = 3;
static constexpr int KITERS = K / BK;    // 64

static constexpr int A_BYTES = BM * BK * 2;              // 16384 (A: 128 rows x 128B)
static constexpr int B_BYTES = BK * BN * 2;              // 16384 (B: 64 k-rows x 256B)
static constexpr int STAGE_BYTES = A_BYTES + B_BYTES;    // 32768
static constexpr int SMEM_TOTAL = STAGES * STAGE_BYTES;  // 98304 (x2 CTAs/SM)

__device__ __half g_x16[(size_t)M * K];   // 16 MB : x fp16, [M][K] k-contiguous
__device__ __half g_wt [(size_t)K * N];   // 32 MB : dequant W fp16, [K][N] n-contiguous

// ---------------------------------------------------------------------------
__device__ __forceinline__ uint32_t smem_u32(const void* p) {
    uint32_t a;
    asm("{ .reg .u64 t; cvta.to.shared.u64 t, %1; cvt.u32.u64 %0, t; }"
        : "=r"(a) : "l"(p));
    return a;
}
__device__ __forceinline__ void cp_async_16(uint32_t dst, const void* src) {
    asm volatile("cp.async.cg.shared.global [%0], [%1], 16;"
                 :: "r"(dst), "l"(src) : "memory");
}
__device__ __forceinline__ void cp_commit() {
    asm volatile("cp.async.commit_group;" ::: "memory");
}
__device__ __forceinline__ void cp_wait1() {
    asm volatile("cp.async.wait_group 1;" ::: "memory");
}
__device__ __forceinline__ void ldsm_x4(uint32_t* r, uint32_t addr) {
    asm volatile("ldmatrix.sync.aligned.m8n8.x4.shared.b16 {%0,%1,%2,%3}, [%4];"
                 : "=r"(r[0]), "=r"(r[1]), "=r"(r[2]), "=r"(r[3]) : "r"(addr));
}
__device__ __forceinline__ void ldsm_x4_trans(uint32_t* r, uint32_t addr) {
    asm volatile("ldmatrix.sync.aligned.m8n8.x4.trans.shared.b16 {%0,%1,%2,%3}, [%4];"
                 : "=r"(r[0]), "=r"(r[1]), "=r"(r[2]), "=r"(r[3]) : "r"(addr));
}
__device__ __forceinline__ void mma16816(float* c, const uint32_t* a,
                                         uint32_t b0, uint32_t b1) {
    asm volatile(
        "mma.sync.aligned.m16n8k16.row.col.f32.f16.f16.f32 "
        "{%0,%1,%2,%3}, {%4,%5,%6,%7}, {%8,%9}, {%0,%1,%2,%3};"
        : "+f"(c[0]), "+f"(c[1]), "+f"(c[2]), "+f"(c[3])
        : "r"(a[0]), "r"(a[1]), "r"(a[2]), "r"(a[3]), "r"(b0), "r"(b1));
}

// ============================================================================
// Kernel 1: merged streaming prepass (no smem anywhere).
//   blocks [0, 8192):      dequant-NT: wt[k][n] = f(w[k][n]) * sc[k>>7][n]
//   blocks [8192, 12288):  x fp32 -> fp16
// ============================================================================
static constexpr int DQ_BLOCKS = 8192;   // 2.097M threads x 8 halves
__global__ void __launch_bounds__(256) prep_kernel(const float4* __restrict__ x,
                                                   uint4* __restrict__ xo,
                                                   const int* __restrict__ w,
                                                   const float* __restrict__ sc,
                                                   __half* __restrict__ wt) {
    const int bid = blockIdx.x;
    const int tid = threadIdx.x;

    if (bid >= DQ_BLOCKS) {
        size_t i = (size_t)(bid - DQ_BLOCKS) * 256 + tid;
        float4 a = x[2 * i];
        float4 b = x[2 * i + 1];
        __half2 h0 = __floats2half2_rn(a.x, a.y);
        __half2 h1 = __floats2half2_rn(a.z, a.w);
        __half2 h2 = __floats2half2_rn(b.x, b.y);
        __half2 h3 = __floats2half2_rn(b.z, b.w);
        uint4 v;
        v.x = reinterpret_cast<uint32_t&>(h0);
        v.y = reinterpret_cast<uint32_t&>(h1);
        v.z = reinterpret_cast<uint32_t&>(h2);
        v.w = reinterpret_cast<uint32_t&>(h3);
        xo[i] = v;
        return;
    }

    // dequant-NT: idx -> (k, 8-n group); fully coalesced, no smem.
    size_t idx = (size_t)bid * 256 + tid;          // 0 .. 2,097,151
    int k  = (int)(idx >> 9);                      // 0..4095
    int n8 = ((int)idx & 511) * 8;                 // 0..4088
    const int*   wp  = w  + (size_t)k * 4096 + n8;
    const float* scp = sc + (size_t)(k >> 7) * 4096 + n8;
    int4   q0 = *(const int4*)(wp);
    int4   q1 = *(const int4*)(wp + 4);
    float4 f0 = *(const float4*)(scp);
    float4 f1 = *(const float4*)(scp + 4);
    __half2 h0 = __floats2half2_rn((float)q0.x * f0.x, (float)q0.y * f0.y);
    __half2 h1 = __floats2half2_rn((float)q0.z * f0.z, (float)q0.w * f0.w);
    __half2 h2 = __floats2half2_rn((float)q1.x * f1.x, (float)q1.y * f1.y);
    __half2 h3 = __floats2half2_rn((float)q1.z * f1.z, (float)q1.w * f1.w);
    uint4 v;
    v.x = reinterpret_cast<uint32_t&>(h0);
    v.y = reinterpret_cast<uint32_t&>(h1);
    v.z = reinterpret_cast<uint32_t&>(h2);
    v.w = reinterpret_cast<uint32_t&>(h3);
    *(uint4*)(wt + (size_t)k * 4096 + n8) = v;
}

// ============================================================================
// Kernel 2: fp16 HMMA GEMM (R9 core; B n-major via ldmatrix.trans)
//   BM=128 x BN=128 x BK=64, 8 warps (2m x 4n, warp 64m x 32n),
//   3-stage cp.async ring, one __syncthreads per iter, 2 CTAs/SM.
// ============================================================================
__global__ void __launch_bounds__(256, 2)
gemm_kernel(const __half* __restrict__ A, const __half* __restrict__ B,
            float* __restrict__ out) {
    extern __shared__ char smem[];
    const uint32_t sb = smem_u32(smem);

    const int tid  = threadIdx.x;
    const int wid  = tid >> 5;
    const int lane = tid & 31;

    const int mt = blockIdx.x & 15;
    const int nt = blockIdx.x >> 4;
    const int m0 = mt * BM;
    const int n0 = nt * BN;

    const int wm = (wid & 1) * 64;
    const int wn = (wid >> 1) * 32;

    // ---- A cp.async (verified): rows of m, 128B of k ----
    const int arow = tid >> 3;           // 0..31
    const int acc_ = tid & 7;
    const uint32_t a_dst0 = (uint32_t)arow * 128 + (((acc_ ^ (arow & 7)) << 4));
    const __half* a_base = A + (size_t)(m0 + arow) * K + acc_ * 8;

    // ---- B cp.async: 64 k-rows x 256B of n; swizzle j ^= (k&7)<<1 ----
    const int brow = tid >> 4;           // 0..15 (+16 per i; (brow+16)&7 == brow&7)
    const int bj   = tid & 15;
    const uint32_t b_dst0 = A_BYTES + (uint32_t)brow * 256 +
                            (((uint32_t)(bj ^ ((brow & 7) << 1))) << 4);
    const __half* b_base = B + (size_t)brow * N + n0 + bj * 8;

    // ---- A ldsm (verified mapping) ----
    const int a_hi = lane >> 4;
    uint32_t offA[4];
    #pragma unroll
    for (int mi = 0; mi < 4; ++mi) {
        int r = wm + mi * 16 + (lane & 15);
        offA[mi] = (uint32_t)r * 128;    // + ((ks*2 + a_hi) ^ (r&7))<<4 at use
    }
    int a_rm[4];
    #pragma unroll
    for (int mi = 0; mi < 4; ++mi) a_rm[mi] = (wm + mi * 16 + (lane & 15)) & 7;

    // ---- B ldsm.trans: lane -> (k_off, n-chunk); ks-invariant swizzle ----
    const int k_off  = (lane & 7) + (((lane >> 4) & 1) << 3);   // 0..15
    const int n_off8 = (lane >> 3) & 1;                          // chunk +0/+1
    uint32_t offB[2];
    #pragma unroll
    for (int nb = 0; nb < 2; ++nb) {
        uint32_t j = (uint32_t)(wn >> 3) + nb * 2 + n_off8;      // logical 16B chunk
        offB[nb] = A_BYTES + (uint32_t)k_off * 256 +
                   ((j ^ (((uint32_t)k_off & 7) << 1)) << 4);
        // + ks*4096 bytes per k-step (16 rows x 256B)
    }

    float acc[4][4][4];
    #pragma unroll
    for (int mi = 0; mi < 4; ++mi)
        #pragma unroll
        for (int ni = 0; ni < 4; ++ni)
            #pragma unroll
            for (int j = 0; j < 4; ++j) acc[mi][ni][j] = 0.f;

    auto load_stage = [&](int it, int stage) {
        uint32_t sd = sb + stage * STAGE_BYTES;
        size_t akoff = (size_t)it * BK;                 // halves along k (A)
        size_t bkoff = (size_t)it * BK * N;             // 64 k-rows (B)
        #pragma unroll
        for (int i = 0; i < 4; ++i)                     // A: m-rows arow + 32i
            cp_async_16(sd + a_dst0 + i * (32 * 128), a_base + akoff + (size_t)(32 * i) * K);
        #pragma unroll
        for (int i = 0; i < 4; ++i)                     // B: k-rows brow + 16i
            cp_async_16(sd + b_dst0 + i * (16 * 256),
                        b_base + bkoff + (size_t)(16 * i) * N);
    };

    load_stage(0, 0); cp_commit();
    load_stage(1, 1); cp_commit();

    int stage_w = 2;
    #pragma unroll 1
    for (int it = 0; it < KITERS; ++it) {
        cp_wait1();
        __syncthreads();

        if (it + 2 < KITERS) load_stage(it + 2, stage_w);
        cp_commit();
        stage_w = (stage_w == 2) ? 0 : stage_w + 1;

        const uint32_t sA = sb + (it % STAGES) * STAGE_BYTES;

        #pragma unroll
        for (int ks = 0; ks < 4; ++ks) {
            uint32_t a_frag[4][4], b_frag[2][4];
            #pragma unroll
            for (int mi = 0; mi < 4; ++mi) {
                uint32_t c = (uint32_t)((ks * 2 + a_hi) ^ a_rm[mi]) << 4;
                ldsm_x4(a_frag[mi], sA + offA[mi] + c);
            }
            #pragma unroll
            for (int nb = 0; nb < 2; ++nb)
                ldsm_x4_trans(b_frag[nb], sA + offB[nb] + (uint32_t)ks * 4096);
            // trans regs: r0=k-lo/n-lo, r1=k-lo/n-hi, r2=k-hi/n-lo, r3=k-hi/n-hi
            #pragma unroll
            for (int mi = 0; mi < 4; ++mi)
                #pragma unroll
                for (int nb = 0; nb < 2; ++nb) {
                    mma16816(acc[mi][2 * nb + 0], a_frag[mi], b_frag[nb][0], b_frag[nb][2]);
                    mma16816(acc[mi][2 * nb + 1], a_frag[mi], b_frag[nb][1], b_frag[nb][3]);
                }
        }
    }

    // ---- epilogue (verified c-fragment mapping) ----
    const int r0 = m0 + wm + (lane >> 2);
    const int c0 = n0 + wn + (lane & 3) * 2;
    #pragma unroll
    for (int mi = 0; mi < 4; ++mi) {
        #pragma unroll
        for (int ni = 0; ni < 4; ++ni) {
            int r = r0 + mi * 16;
            int c = c0 + ni * 8;
            *(float2*)(out + (size_t)r * N + c)       = make_float2(acc[mi][ni][0], acc[mi][ni][1]);
            *(float2*)(out + (size_t)(r + 8) * N + c) = make_float2(acc[mi][ni][2], acc[mi][ni][3]);
        }
    }
}

// ============================================================================
// Host launch
// ============================================================================
extern "C" void kernel_launch(void* const* d_in, const int* in_sizes, int n_in,
                              void* d_out, int out_size) {
    const float* x  = (const float*)d_in[0];
    const int*   w  = (const int*)d_in[1];     // int8 promoted to int32 by harness
    const float* sc = (const float*)d_in[2];
    float* out = (float*)d_out;

    void* p_x16 = nullptr;
    void* p_wt  = nullptr;
    cudaGetSymbolAddress(&p_x16, g_x16);
    cudaGetSymbolAddress(&p_wt,  g_wt);

    prep_kernel<<<DQ_BLOCKS + 4096, 256>>>((const float4*)x, (uint4*)p_x16,
                                           w, sc, (__half*)p_wt);

    cudaFuncSetAttribute(gemm_kernel, cudaFuncAttributeMaxDynamicSharedMemorySize,
                         SMEM_TOTAL);
    gemm_kernel<<<(M / BM) * (N / BN), 256, SMEM_TOTAL>>>(
        (const __half*)p_x16, (const __half*)p_wt, out);
}

// round 13
// speedup vs baseline: 1.1182x; 1.1182x over previous
#include <cuda_runtime.h>
#include <cuda_fp16.h>
#include <cstdint>

// ============================================================================
// out[m,n] = sum_k x[m,k] * (w[k/128, k%128, n] * scaler[k/128, n])
//   x: [2,1024,4096] f32 (M=2048,K=4096)  w: [32,128,4096] INT32  sc: [32,4096]
//
// R13: kernel-level software pipeline. K split in halves:
//   prep(h0) -> [ gemm0(k<2048, write) || prep(h1) ] -> gemm1(k>=2048, accum)
// Fork-join expressed with a side stream + events (host code runs only at
// graph-capture time; branches become parallel graph nodes). GEMM body is
// byte-identical to the verified R9 kernel (plus k-offset + uniform acc
// branch); prep is the verified R10 body parameterized by (k_lo, s_lo).
// ============================================================================

static constexpr int M = 2048;
static constexpr int N = 4096;
static constexpr int K = 4096;

static constexpr int BM = 128;
static constexpr int BN = 128;
static constexpr int BK = 64;
static constexpr int STAGES = 3;
static constexpr int KITERS_H = 2048 / BK;   // 32 iters per half-K pass

static constexpr int A_BYTES = BM * BK * 2;              // 16384
static constexpr int B_BYTES = BN * BK * 2;              // 16384
static constexpr int STAGE_BYTES = A_BYTES + B_BYTES;    // 32768
static constexpr int SMEM_TOTAL = STAGES * STAGE_BYTES;  // 98304 (x2 CTAs/SM)

__device__ __half g_x16[(size_t)M * K];   // 16 MB : x fp16, [M][K]
__device__ __half g_wt [(size_t)N * K];   // 32 MB : dequant W^T fp16, [N][K]

// ---------------------------------------------------------------------------
__device__ __forceinline__ uint32_t smem_u32(const void* p) {
    uint32_t a;
    asm("{ .reg .u64 t; cvta.to.shared.u64 t, %1; cvt.u32.u64 %0, t; }"
        : "=r"(a) : "l"(p));
    return a;
}
__device__ __forceinline__ void cp_async_16(uint32_t dst, const void* src) {
    asm volatile("cp.async.cg.shared.global [%0], [%1], 16;"
                 :: "r"(dst), "l"(src) : "memory");
}
__device__ __forceinline__ void cp_commit() {
    asm volatile("cp.async.commit_group;" ::: "memory");
}
__device__ __forceinline__ void cp_wait1() {
    asm volatile("cp.async.wait_group 1;" ::: "memory");
}
__device__ __forceinline__ void ldsm_x4(uint32_t* r, uint32_t addr) {
    asm volatile("ldmatrix.sync.aligned.m8n8.x4.shared.b16 {%0,%1,%2,%3}, [%4];"
                 : "=r"(r[0]), "=r"(r[1]), "=r"(r[2]), "=r"(r[3]) : "r"(addr));
}
__device__ __forceinline__ void mma16816(float* c, const uint32_t* a,
                                         uint32_t b0, uint32_t b1) {
    asm volatile(
        "mma.sync.aligned.m16n8k16.row.col.f32.f16.f16.f32 "
        "{%0,%1,%2,%3}, {%4,%5,%6,%7}, {%8,%9}, {%0,%1,%2,%3};"
        : "+f"(c[0]), "+f"(c[1]), "+f"(c[2]), "+f"(c[3])
        : "r"(a[0]), "r"(a[1]), "r"(a[2]), "r"(a[3]), "r"(b0), "r"(b1));
}

// ============================================================================
// Kernel 1: half-K prepass (verified R10 bodies, range-parameterized).
//   blocks [0, 1024):    dequant+transpose for s in [s_lo, s_lo+16)
//   blocks [1024, 3072): x fp32 -> fp16 for k in [k_lo, k_lo+2048)
// ============================================================================
__global__ void __launch_bounds__(256) prep_kernel(const float* __restrict__ x,
                                                   __half* __restrict__ xo,
                                                   const int* __restrict__ w,
                                                   const float* __restrict__ sc,
                                                   __half* __restrict__ wt,
                                                   int k_lo, int s_lo) {
    __shared__ __half tile[128][66];
    const int bid = blockIdx.x;
    const int tid = threadIdx.x;

    if (bid >= 1024) {
        // ---- convert_x half: 2048 blocks x 256 thr x 8 halves ----
        size_t j = (size_t)(bid - 1024) * 256 + tid;    // 0 .. 524287
        int m  = (int)(j >> 8);                          // 0..2047
        int kk = ((int)j & 255) * 8 + k_lo;              // k chunk of 8
        const float4* px = (const float4*)(x + (size_t)m * K + kk);
        float4 a = px[0];
        float4 b = px[1];
        __half2 h0 = __floats2half2_rn(a.x, a.y);
        __half2 h1 = __floats2half2_rn(a.z, a.w);
        __half2 h2 = __floats2half2_rn(b.x, b.y);
        __half2 h3 = __floats2half2_rn(b.z, b.w);
        uint4 v;
        v.x = reinterpret_cast<uint32_t&>(h0);
        v.y = reinterpret_cast<uint32_t&>(h1);
        v.z = reinterpret_cast<uint32_t&>(h2);
        v.w = reinterpret_cast<uint32_t&>(h3);
        *(uint4*)(xo + (size_t)m * K + kk) = v;
        return;
    }

    // ---- dequant half: s = s_lo + bid>>6, 64-wide n strip = bid&63 ----
    const int s  = s_lo + (bid >> 6);
    const int n0 = (bid & 63) * 64;

    #pragma unroll
    for (int i = tid; i < 128 * 16; i += 256) {
        int c = i >> 4;
        int n = (i & 15) * 4;
        const int4   q = *(const int4*)(w + ((size_t)(s * 128 + c)) * 4096 + n0 + n);
        const float4 f = *(const float4*)(sc + (size_t)s * 4096 + n0 + n);
        __half2 h0 = __floats2half2_rn((float)q.x * f.x, (float)q.y * f.y);
        __half2 h1 = __floats2half2_rn((float)q.z * f.z, (float)q.w * f.w);
        *(__half2*)&tile[c][n]     = h0;
        *(__half2*)&tile[c][n + 2] = h1;
    }
    __syncthreads();

    #pragma unroll
    for (int i = tid; i < 64 * 32; i += 256) {
        int cq = i & 31;
        int n  = i >> 5;
        int c0 = cq * 4;
        uint32_t lo = (uint32_t)__half_as_ushort(tile[c0 + 0][n]) |
                      ((uint32_t)__half_as_ushort(tile[c0 + 1][n]) << 16);
        uint32_t hi = (uint32_t)__half_as_ushort(tile[c0 + 2][n]) |
                      ((uint32_t)__half_as_ushort(tile[c0 + 3][n]) << 16);
        uint2 v; v.x = lo; v.y = hi;
        *(uint2*)(wt + (size_t)(n0 + n) * 4096 + s * 128 + c0) = v;
    }
}

// ============================================================================
// Kernel 2: fp16 HMMA GEMM over one K-half (R9 body + k0 offset + acc flag)
//   BM=128 x BN=128 x BK=64, 8 warps (2m x 4n, warp 64m x 32n),
//   3-stage cp.async ring, one __syncthreads per iter, 2 CTAs/SM.
// ============================================================================
__global__ void __launch_bounds__(256, 2)
gemm_kernel(const __half* __restrict__ A, const __half* __restrict__ B,
            float* __restrict__ out, int k0, int acc_flag) {
    extern __shared__ char smem[];
    const uint32_t sb = smem_u32(smem);

    const int tid  = threadIdx.x;
    const int wid  = tid >> 5;
    const int lane = tid & 31;

    const int mt = blockIdx.x & 15;
    const int nt = blockIdx.x >> 4;
    const int m0 = mt * BM;
    const int n0 = nt * BN;

    const int wm = (wid & 1) * 64;
    const int wn = (wid >> 1) * 32;

    // ---- cp.async bases (R9) + k0 offset ----
    const int row0 = tid >> 3;
    const int cc   = tid & 7;
    const uint32_t dst0 = (uint32_t)row0 * 128 + (((cc ^ (row0 & 7)) << 4));
    const __half* a_base = A + (size_t)(m0 + row0) * K + cc * 8 + k0;
    const __half* b_base = B + (size_t)(n0 + row0) * K + cc * 8 + k0;

    // ---- ldmatrix lane addressing (verified R9 mapping) ----
    int a_row[4];
    #pragma unroll
    for (int mi = 0; mi < 4; ++mi) a_row[mi] = wm + mi * 16 + (lane & 15);
    const int a_hi = lane >> 4;
    const int b_hi = (lane >> 3) & 1;
    int b_row[2];
    #pragma unroll
    for (int nb = 0; nb < 2; ++nb)
        b_row[nb] = wn + nb * 16 + (lane & 7) + 8 * (lane >> 4);

    float acc[4][4][4];
    #pragma unroll
    for (int mi = 0; mi < 4; ++mi)
        #pragma unroll
        for (int ni = 0; ni < 4; ++ni)
            #pragma unroll
            for (int j = 0; j < 4; ++j) acc[mi][ni][j] = 0.f;

    auto load_stage = [&](int it, int stage) {
        uint32_t sd = sb + stage * STAGE_BYTES;
        size_t koff = (size_t)it * BK;
        #pragma unroll
        for (int i = 0; i < 4; ++i)
            cp_async_16(sd + dst0 + i * (32 * 128), a_base + koff + (size_t)(32 * i) * K);
        #pragma unroll
        for (int i = 0; i < 4; ++i)
            cp_async_16(sd + A_BYTES + dst0 + i * (32 * 128),
                        b_base + koff + (size_t)(32 * i) * K);
    };

    load_stage(0, 0); cp_commit();
    load_stage(1, 1); cp_commit();

    int stage_w = 2;
    #pragma unroll 1
    for (int it = 0; it < KITERS_H; ++it) {
        cp_wait1();
        __syncthreads();

        if (it + 2 < KITERS_H) load_stage(it + 2, stage_w);
        cp_commit();
        stage_w = (stage_w == 2) ? 0 : stage_w + 1;

        const uint32_t sA = sb + (it % STAGES) * STAGE_BYTES;
        const uint32_t sB = sA + A_BYTES;

        #pragma unroll
        for (int ks = 0; ks < 4; ++ks) {
            uint32_t a_frag[4][4], b_frag[2][4];
            #pragma unroll
            for (int mi = 0; mi < 4; ++mi) {
                uint32_t c = (uint32_t)((ks * 2 + a_hi) ^ (a_row[mi] & 7)) << 4;
                ldsm_x4(a_frag[mi], sA + a_row[mi] * 128 + c);
            }
            #pragma unroll
            for (int nb = 0; nb < 2; ++nb) {
                uint32_t c = (uint32_t)((ks * 2 + b_hi) ^ (b_row[nb] & 7)) << 4;
                ldsm_x4(b_frag[nb], sB + b_row[nb] * 128 + c);
            }
            #pragma unroll
            for (int mi = 0; mi < 4; ++mi)
                #pragma unroll
                for (int nb = 0; nb < 2; ++nb) {
                    mma16816(acc[mi][2 * nb + 0], a_frag[mi], b_frag[nb][0], b_frag[nb][1]);
                    mma16816(acc[mi][2 * nb + 1], a_frag[mi], b_frag[nb][2], b_frag[nb][3]);
                }
        }
    }

    // ---- epilogue (verified mapping; optional accumulate for pass 2) ----
    const int r0 = m0 + wm + (lane >> 2);
    const int c0 = n0 + wn + (lane & 3) * 2;
    #pragma unroll
    for (int mi = 0; mi < 4; ++mi) {
        #pragma unroll
        for (int ni = 0; ni < 4; ++ni) {
            int r = r0 + mi * 16;
            int c = c0 + ni * 8;
            float2 v0 = make_float2(acc[mi][ni][0], acc[mi][ni][1]);
            float2 v1 = make_float2(acc[mi][ni][2], acc[mi][ni][3]);
            float2* p0 = (float2*)(out + (size_t)r * N + c);
            float2* p1 = (float2*)(out + (size_t)(r + 8) * N + c);
            if (acc_flag) {
                float2 o0 = *p0, o1 = *p1;
                v0.x += o0.x; v0.y += o0.y;
                v1.x += o1.x; v1.y += o1.y;
            }
            *p0 = v0;
            *p1 = v1;
        }
    }
}

// ============================================================================
// Host launch: prep(h0) -> [ gemm0 || prep(h1) ] -> gemm1(accumulate)
// (host code runs once at graph capture; fork via side stream + events)
// ============================================================================
extern "C" void kernel_launch(void* const* d_in, const int* in_sizes, int n_in,
                              void* d_out, int out_size) {
    const float* x  = (const float*)d_in[0];
    const int*   w  = (const int*)d_in[1];     // int8 promoted to int32 by harness
    const float* sc = (const float*)d_in[2];
    float* out = (float*)d_out;

    void* p_x16 = nullptr;
    void* p_wt  = nullptr;
    cudaGetSymbolAddress(&p_x16, g_x16);
    cudaGetSymbolAddress(&p_wt,  g_wt);
    __half* x16 = (__half*)p_x16;
    __half* wt  = (__half*)p_wt;

    cudaFuncSetAttribute(gemm_kernel, cudaFuncAttributeMaxDynamicSharedMemorySize,
                         SMEM_TOTAL);

    cudaStream_t s1;
    cudaStreamCreateWithFlags(&s1, cudaStreamNonBlocking);
    cudaEvent_t e0, e1;
    cudaEventCreateWithFlags(&e0, cudaEventDisableTiming);
    cudaEventCreateWithFlags(&e1, cudaEventDisableTiming);

    // prep half 0 (k in [0,2048), s in [0,16))
    prep_kernel<<<3072, 256>>>(x, x16, w, sc, wt, 0, 0);

    // fork: s1 depends on prep0
    cudaEventRecord(e0, 0);
    cudaStreamWaitEvent(s1, e0, 0);

    // branch A (main stream): gemm pass 0 (writes out)
    gemm_kernel<<<(M / BM) * (N / BN), 256, SMEM_TOTAL>>>(x16, wt, out, 0, 0);

    // branch B (side stream): prep half 1 (k in [2048,4096), s in [16,32))
    prep_kernel<<<3072, 256, 0, s1>>>(x, x16, w, sc, wt, 2048, 16);

    // join: main stream waits for prep1, then gemm pass 1 (accumulates)
    cudaEventRecord(e1, s1);
    cudaStreamWaitEvent(0, e1, 0);
    gemm_kernel<<<(M / BM) * (N / BN), 256, SMEM_TOTAL>>>(x16, wt, out, 2048, 1);
    // note: s1/e0/e1 intentionally not destroyed here -- destroying objects
    // attached to an in-progress stream capture invalidates the capture.
}